// round 6
// baseline (speedup 1.0000x reference)
#include <cuda_runtime.h>
#include <cuda_bf16.h>
#include <cstdint>

// MaxUnpooling2DMod: out[b, y(idx), x(idx), c] += in[b,h,w,c]
//   in  [8,128,128,64] -> 2^23 floats, out [8,256,256,64] -> 2^25 floats
// decode: out_off = (b << 22) + (idx & ~63) + (lin & 63)
//
// Single fused kernel, 9 block-groups of 512 blocks:
//   group g: zero slab g (g<8), signal; spin on slab g-1 ready, scatter batch g-1 (g>=1).
// Blocks launch in bid order => predecessor groups always make progress (their
// zero phase precedes their spin) => no deadlock. ~2.3 groups co-resident =>
// zeros / atomics / drain of adjacent batches overlap with no kernel boundaries.

static constexpr int BLOCK       = 256;
static constexpr int GROUP_BLKS  = 512;
static constexpr int NGROUPS     = 9;
static constexpr int GRID        = GROUP_BLKS * NGROUPS;      // 4608
static constexpr int GROUP_THREADS = GROUP_BLKS * BLOCK;      // 131072
static constexpr int SLAB_F4     = (1 << 22) / 4;             // 1,048,576 float4/slab
static constexpr int ZERO_PER_T  = SLAB_F4 / GROUP_THREADS;   // 8
static constexpr int ELEMS_PER_T = (1 << 20) / GROUP_THREADS; // 8

__device__ unsigned g_ready[8];

__global__ void reset_counters_kernel()
{
    if (threadIdx.x < 8) g_ready[threadIdx.x] = 0;
}

__global__ void __launch_bounds__(BLOCK)
unpool_fused_pipe_kernel(const float* __restrict__ in,
                         const int*   __restrict__ idx,
                         float*       __restrict__ out)
{
    const int g = blockIdx.x / GROUP_BLKS;            // group 0..8
    const int r = blockIdx.x - g * GROUP_BLKS;        // block within group
    const int t = (r << 8) | threadIdx.x;             // thread within group

    // ---- streaming loads for the scatter phase (independent, start early) ----
    const int bs = g - 1;                             // batch to scatter
    float4 v0, v1;
    int4   id0, id1;
    int    e0 = 0;
    if (bs >= 0) {
        e0 = (bs << 20) + t * ELEMS_PER_T;
        const float4* in4  = reinterpret_cast<const float4*>(in)  + (e0 >> 2);
        const int4*   idx4 = reinterpret_cast<const int4*>(idx)   + (e0 >> 2);
        v0  = __ldcs(in4 + 0);   v1  = __ldcs(in4 + 1);
        id0 = __ldcs(idx4 + 0);  id1 = __ldcs(idx4 + 1);
    }

    // ---- zero phase: slab g (no dependency) ----
    if (g < 8) {
        float4* o4 = reinterpret_cast<float4*>(out) + (size_t)g * SLAB_F4;
        const float4 z = make_float4(0.f, 0.f, 0.f, 0.f);
        #pragma unroll
        for (int j = 0; j < ZERO_PER_T; j++)
            o4[t + j * GROUP_THREADS] = z;

        __syncthreads();                               // all block stores done
        if (threadIdx.x == 0) {
            // release-add: publishes this block's zero stores gpu-wide
            asm volatile("red.release.gpu.global.add.u32 [%0], 1;"
                         :: "l"(&g_ready[g]) : "memory");
        }
    }

    // ---- scatter phase: wait for slab bs fully zeroed, then atomics ----
    if (bs >= 0) {
        if (threadIdx.x == 0) {
            const unsigned* p = &g_ready[bs];
            unsigned v;
            while (true) {
                asm volatile("ld.acquire.gpu.global.u32 %0, [%1];"
                             : "=r"(v) : "l"(p) : "memory");
                if (v >= (unsigned)GROUP_BLKS) break;
                __nanosleep(128);
            }
        }
        __syncthreads();                               // propagate acquire cta-wide

        const int base = bs << 22;
        const int c0   = e0 & 63;                      // e0 multiple of 8
        atomicAdd(out + base + (id0.x & ~63) + (c0 + 0), v0.x);
        atomicAdd(out + base + (id0.y & ~63) + (c0 + 1), v0.y);
        atomicAdd(out + base + (id0.z & ~63) + (c0 + 2), v0.z);
        atomicAdd(out + base + (id0.w & ~63) + (c0 + 3), v0.w);
        atomicAdd(out + base + (id1.x & ~63) + (c0 + 4), v1.x);
        atomicAdd(out + base + (id1.y & ~63) + (c0 + 5), v1.y);
        atomicAdd(out + base + (id1.z & ~63) + (c0 + 6), v1.z);
        atomicAdd(out + base + (id1.w & ~63) + (c0 + 7), v1.w);
    }
}

extern "C" void kernel_launch(void* const* d_in, const int* in_sizes, int n_in,
                              void* d_out, int out_size)
{
    const float* in  = (const float*)d_in[0];
    const int*   idx = (const int*)d_in[1];
    float*       out = (float*)d_out;

    reset_counters_kernel<<<1, 32>>>();
    unpool_fused_pipe_kernel<<<GRID, BLOCK>>>(in, idx, out);
}